// round 13
// baseline (speedup 1.0000x reference)
#include <cuda_runtime.h>
#include <cuda_fp16.h>

#define Hh 256
#define Ww 512
#define Bn 4
#define SPANK 11
#define NOFF 242
#define NPIX (Bn*Hh*Ww)

#define RGB_S 8.493218083f
#define DEP_S 4.2466090415f

#define TBX 32
#define TBY 16
#define PERW 28
#define HYr 27
#define NHX 57
#define ROWB (PERW*16)       // 448
#define PLANE (HYr*ROWB)     // 12096
#define USO (PLANE/2)

__device__ uint4  g_PK[NPIX];
__device__ float  g_aF[256], g_aB[256];
__device__ double g_ce[3];
__device__ float  g_rowFull[Hh];
__device__ float  g_rowHead[Hh][12];
__device__ float  g_rowTail[Hh][12];
__device__ int    g_map[256];   // (slot<<10)|(dx<<5)|(dy+16)

__device__ __forceinline__ __half2 h2ex2(__half2 x) {
    unsigned r;
    asm("ex2.approx.f16x2 %0, %1;" : "=r"(r) : "r"(*(unsigned*)&x));
    return *(__half2*)&r;
}

__device__ __forceinline__ int residue8(int dx, int dy) {
    int w;
    if (dy & 1) w = 756 - 28 * dx - (dy + 1) / 2;
    else        w = -28 * dx - dy / 2;
    return ((w % 8) + 8) % 8;
}

// ---------------- kernel 0: zero accumulators + build conflict-free map ----
__global__ void k_zero() {
    int t = threadIdx.x;
    if (t < 256) { g_aF[t] = 0.f; g_aB[t] = 0.f; }
    if (t < 3) g_ce[t] = 0.0;
    if (t == 0) {
        int len[8];
        int lists[8][34];
        #pragma unroll
        for (int r = 0; r < 8; r++) len[r] = 0;
        for (int id = 0; id < NOFF; id++) {
            int dx = id / 22 + 1;
            int rr = id - (dx - 1) * 22;
            int dy = rr - SPANK; dy += (dy >= 0);
            int r = residue8(dx, dy);
            lists[r][len[r]++] = (id << 10) | (dx << 5) | (dy + 16);
        }
        // dummies targeted at deficient residues (results discarded)
        const int ddx[4] = {1, 1, 1, 1};
        const int ddy[4] = {8, 4, 7, 3};     // residues 0,2,4,6
        const int drr[4] = {0, 2, 4, 6};
        const int dcn[4] = {4, 4, 3, 3};     // totals -> {32,33,32,33,30,33,30,33}
        int ds = NOFF;
        for (int k = 0; k < 4; k++)
            for (int i = 0; i < dcn[k]; i++)
                lists[drr[k]][len[drr[k]]++] = (ds++ << 10) | (ddx[k] << 5) | (ddy[k] + 16);
        // deal: each quarter-group of 8 lanes gets one offset per residue
        int out = 0;
        for (int qg = 0; qg < 32; qg++) {
            for (int p = 0; p < 8; p++) {
                int r = p;
                if (len[r] == 0) {
                    int best = 0;
                    for (int j = 1; j < 8; j++) if (len[j] > len[best]) best = j;
                    r = best;
                }
                g_map[out++] = lists[r][--len[r]];
            }
        }
    }
}

__global__ void k_prep(const float* __restrict__ logit,
                       const long long* __restrict__ target,
                       const float* __restrict__ image,
                       const float* __restrict__ depth,
                       const float* __restrict__ dstm) {
    int idx = blockIdx.x * blockDim.x + threadIdx.x;
    float ce_d = 0.f, ce_a = 0.f, d_s = 0.f;
    if (idx < NPIX) {
        int b = idx / (Hh * Ww);
        int p = idx - b * (Hh * Ww);
        const float* lg = logit + (size_t)b * 3 * Hh * Ww + p;
        float l0 = lg[0], l1 = lg[Hh * Ww], l2 = lg[2 * Hh * Ww];
        float m = fmaxf(l0, fmaxf(l1, l2));
        float e0 = __expf(l0 - m), e1 = __expf(l1 - m), e2 = __expf(l2 - m);
        float s = e0 + e1 + e2;
        float inv = 1.f / s;
        const float* im = image + (size_t)b * 3 * Hh * Ww + p;
        float dv = dstm[idx];
        __half2 h0 = __floats2half2_rn(im[0] * RGB_S, im[Hh * Ww] * RGB_S);
        __half2 h1 = __floats2half2_rn(im[2 * Hh * Ww] * RGB_S, depth[idx] * DEP_S);
        __half2 h2 = __floats2half2_rn(e0 * inv, e1 * inv);
        __half2 h3 = __floats2half2_rn(1.0f, dv);
        uint4 pk;
        pk.x = *(unsigned*)&h0; pk.y = *(unsigned*)&h1;
        pk.z = *(unsigned*)&h2; pk.w = *(unsigned*)&h3;
        g_PK[idx] = pk;
        long long t = target[idx];
        float lt = (t == 0) ? l0 : ((t == 1) ? l1 : l2);
        float lce = m + __logf(s) - lt;
        ce_d = lce * dv; ce_a = lce; d_s = dv;
    }
    #pragma unroll
    for (int s = 16; s; s >>= 1) {
        ce_d += __shfl_xor_sync(0xffffffffu, ce_d, s);
        ce_a += __shfl_xor_sync(0xffffffffu, ce_a, s);
        d_s  += __shfl_xor_sync(0xffffffffu, d_s,  s);
    }
    __shared__ float r0[8], r1[8], r2[8];
    int lane = threadIdx.x & 31, w = threadIdx.x >> 5;
    if (lane == 0) { r0[w] = ce_d; r1[w] = ce_a; r2[w] = d_s; }
    __syncthreads();
    if (threadIdx.x == 0) {
        float a = 0.f, bb = 0.f, c = 0.f;
        #pragma unroll
        for (int i = 0; i < 8; i++) { a += r0[i]; bb += r1[i]; c += r2[i]; }
        atomicAdd(&g_ce[0], (double)a);
        atomicAdd(&g_ce[1], (double)bb);
        atomicAdd(&g_ce[2], (double)c);
    }
}

__global__ void k_rows(const float* __restrict__ dstm) {
    int x = blockIdx.x;
    int tid = threadIdx.x;
    int lane = tid & 31, w = tid >> 5;
    float psum = 0.f;
    for (int b = 0; b < Bn; b++) {
        const float* row = dstm + ((size_t)b * Hh + x) * Ww;
        for (int y = tid; y < Ww; y += 128) psum += row[y];
    }
    #pragma unroll
    for (int s = 16; s; s >>= 1) psum += __shfl_xor_sync(0xffffffffu, psum, s);
    __shared__ float wsum[4];
    if (lane == 0) wsum[w] = psum;
    __syncthreads();
    if (tid == 0)
        g_rowFull[x] = wsum[0] + wsum[1] + wsum[2] + wsum[3];
    if (tid < 32 && lane <= SPANK) {
        float h = 0.f;
        for (int y = 0; y < lane; y++)
            for (int b = 0; b < Bn; b++)
                h += dstm[((size_t)b * Hh + x) * Ww + y];
        g_rowHead[x][lane] = h;
        float t = 0.f;
        for (int e = 1; e <= lane; e++)
            for (int b = 0; b < Bn; b++)
                t += dstm[((size_t)b * Hh + x) * Ww + (Ww - e)];
        g_rowTail[x][lane] = t;
    }
}

// ---- CRF: lanes=offsets (permuted conflict-free), half2 SIMD pixel pairs ----
__global__ __launch_bounds__(128, 4) void k_crf() {
    __shared__ __align__(16) unsigned char buf[4 * PLANE];
    const int b  = blockIdx.z;
    const int r0 = blockIdx.y * TBY;
    const int c0 = blockIdx.x * TBX;
    const int lane = threadIdx.x;
    const int w = threadIdx.y;
    const int tid = w * 32 + lane;

    unsigned short* H = (unsigned short*)buf;
    for (int i = tid; i < HYr * NHX; i += 128) {
        int hy = i / NHX, hx = i - hy * NHX;
        int gy = r0 - SPANK + hy;
        int gx = c0 - 12 + hx;
        uint4 v = make_uint4(0u, 0u, 0u, 0u);
        if (gy >= 0 && gy < Hh && gx >= 0 && gx < Ww)
            v = g_PK[(b * Hh + gy) * Ww + gx];
        const unsigned short* u = (const unsigned short*)&v;
        if (hx < 56) {
            int be = (hy * PERW + (hx >> 1)) * 8 + (hx & 1);
            H[be + 0] = u[0]; H[be + 2] = u[1]; H[be + 4] = u[2]; H[be + 6] = u[3];
            H[be + 2*USO + 0] = u[4]; H[be + 2*USO + 2] = u[5];
            H[be + 2*USO + 4] = u[6]; H[be + 2*USO + 6] = u[7];
        }
        if (hx >= 1) {
            int ho = hx - 1;
            int bo = USO + (hy * PERW + (ho >> 1)) * 8 + (ho & 1);
            H[bo + 0] = u[0]; H[bo + 2] = u[1]; H[bo + 4] = u[2]; H[bo + 6] = u[3];
            H[bo + 2*USO + 0] = u[4]; H[bo + 2*USO + 2] = u[5];
            H[bo + 2*USO + 4] = u[6]; H[bo + 2*USO + 6] = u[7];
        }
    }

    // permuted per-lane offset tables
    int vAdj[8], slotv[8];
    __half2 cd2h[8];
    #pragma unroll
    for (int g = 0; g < 8; g++) {
        int e = g_map[g * 32 + lane];
        int dy = (e & 31) - 16;
        int dx = (e >> 5) & 31;
        slotv[g] = e >> 10;
        cd2h[g] = __float2half2_rn(-0.7213475204444817f * (float)(dx*dx + dy*dy) * (1.f/36.f));
        vAdj[g] = (dy & 1) ? (PLANE - dx * ROWB - 8 * (dy + 1))
                           : (-dx * ROWB - 8 * dy);
    }

    __half2 aF2[8], aB2[8];
    float accF[8], accB[8];
    const __half2 zero2 = __float2half2_rn(0.f);
    const __half2 one2  = __float2half2_rn(1.f);
    #pragma unroll
    for (int g = 0; g < 8; g++) { aF2[g] = zero2; aB2[g] = zero2; accF[g] = 0.f; accB[g] = 0.f; }

    __syncthreads();
    const unsigned char* base = buf;

    for (int rr = 0; rr < 4; rr++) {
        int hy = SPANK + 4 * w + rr;
        for (int t = 0; t < 16; t++) {
            int oRel = (hy * PERW + t + 6) * 16;
            uint4 o0 = *(const uint4*)(base + oRel);
            uint4 o1 = *(const uint4*)(base + oRel + 2 * PLANE);
            __half2 Ro = *(__half2*)&o0.x, Go = *(__half2*)&o0.y;
            __half2 Bo = *(__half2*)&o0.z, Zo = *(__half2*)&o0.w;
            __half2 Y0o = *(__half2*)&o1.x, Y1o = *(__half2*)&o1.y, Do = *(__half2*)&o1.w;
            __half2 A2 = __hadd2(Y0o, Y1o);
            __half2 y2o = __hsub2(one2, A2);
            __half2 B2 = __hsub2(y2o, Y0o);
            __half2 C2 = __hsub2(y2o, Y1o);
            #pragma unroll
            for (int g = 0; g < 8; g++) {
                int va = oRel + vAdj[g];
                uint4 v0 = *(const uint4*)(base + va);
                uint4 v1 = *(const uint4*)(base + va + 2 * PLANE);
                __half2 dR = __hsub2(Ro, *(__half2*)&v0.x);
                __half2 dG = __hsub2(Go, *(__half2*)&v0.y);
                __half2 dB = __hsub2(Bo, *(__half2*)&v0.z);
                __half2 dZ = __hsub2(Zo, *(__half2*)&v0.w);
                __half2 a1 = __hfma2(dR, __hneg2(dR), cd2h[g]);
                a1 = __hfma2(dG, __hneg2(dG), a1);
                a1 = __hfma2(dB, __hneg2(dB), a1);
                __half2 az = __hmul2(dZ, __hneg2(dZ));
                __half2 k2 = __hadd2(h2ex2(a1), h2ex2(az));
                __half2 ct = __hmul2(A2, *(__half2*)&v1.z);
                ct = __hfma2(B2, *(__half2*)&v1.x, ct);
                ct = __hfma2(C2, *(__half2*)&v1.y, ct);
                __half2 kc = __hmul2(k2, ct);
                aF2[g] = __hfma2(kc, *(__half2*)&v1.w, aF2[g]);
                aB2[g] = __hfma2(kc, Do, aB2[g]);
            }
            if ((t & 7) == 7) {
                #pragma unroll
                for (int g = 0; g < 8; g++) {
                    float2 f = __half22float2(aF2[g]);
                    float2 bb = __half22float2(aB2[g]);
                    accF[g] += f.x + f.y;
                    accB[g] += bb.x + bb.y;
                    aF2[g] = zero2; aB2[g] = zero2;
                }
            }
        }
    }

    __syncthreads();
    float* red = (float*)buf;                  // [256 slots][4 warps][2]
    #pragma unroll
    for (int g = 0; g < 8; g++) {
        int id = slotv[g];
        red[(id * 4 + w) * 2 + 0] = accF[g];
        red[(id * 4 + w) * 2 + 1] = accB[g];
    }
    __syncthreads();
    for (int o = tid; o < NOFF; o += 128) {
        float f  = red[o * 8 + 0] + red[o * 8 + 2] + red[o * 8 + 4] + red[o * 8 + 6];
        float bb = red[o * 8 + 1] + red[o * 8 + 3] + red[o * 8 + 5] + red[o * 8 + 7];
        atomicAdd(&g_aF[o], f);
        atomicAdd(&g_aB[o], bb);
    }
}

__global__ void k_final(float* __restrict__ out) {
    __shared__ float  sR[23][Hh];
    __shared__ double sFull[23], sHead[23][12], sTail[23][12];
    __shared__ double rect[23 * 23];
    __shared__ double red[256];
    int tid = threadIdx.x;
    int lane = tid & 31, w8 = tid >> 5;
    {
        int x = tid;
        float full = g_rowFull[x];
        float head[12], tail[12];
        #pragma unroll
        for (int i = 0; i < 12; i++) { head[i] = g_rowHead[x][i]; tail[i] = g_rowTail[x][i]; }
        #pragma unroll
        for (int yi = 0; yi < 23; yi++) {
            int dy = yi - SPANK;
            int c = dy < 0 ? -dy : 0;
            int e = dy > 0 ? dy : 0;
            sR[yi][x] = full - head[c] - tail[e];
        }
    }
    __syncthreads();
    for (int yi = w8; yi < 23; yi += 8) {
        float p = 0.f;
        for (int x = lane; x < Hh; x += 32) p += sR[yi][x];
        #pragma unroll
        for (int s = 16; s; s >>= 1) p += __shfl_xor_sync(0xffffffffu, p, s);
        if (lane == 0) sFull[yi] = (double)p;
        if (lane <= SPANK) {
            float h = 0.f;
            for (int x = 0; x < lane; x++) h += sR[yi][x];
            sHead[yi][lane] = (double)h;
            float t = 0.f;
            for (int e = 1; e <= lane; e++) t += sR[yi][Hh - e];
            sTail[yi][lane] = (double)t;
        }
    }
    __syncthreads();
    for (int t = tid; t < 23 * 23; t += 256) {
        int xi = t / 23, yi = t - xi * 23;
        int dx = xi - SPANK;
        int a = dx < 0 ? -dx : 0;
        int bb = dx > 0 ? dx : 0;
        rect[t] = sFull[yi] - sHead[yi][a] - sTail[yi][bb];
    }
    __syncthreads();
    double e = 0.0;
    if (tid < NOFF) {
        int dx = tid / 22 + 1;
        int r = tid - (dx - 1) * 22;
        int dy = r - SPANK;
        dy += (dy >= 0);
        double denF = rect[(SPANK - dx) * 23 + (SPANK - dy)];
        double denB = rect[(SPANK + dx) * 23 + (SPANK + dy)];
        e = (double)g_aF[tid] / denF + (double)g_aB[tid] / denB;
    }
    red[tid] = e;
    __syncthreads();
    for (int s = 128; s; s >>= 1) {
        if (tid < s) red[tid] += red[tid + s];
        __syncthreads();
    }
    if (tid == 0) {
        out[1] = (float)(red[0] / 529.0);
        double N = (double)NPIX;
        double SA = g_ce[0], SB = g_ce[1], SC = g_ce[2];
        double lo1 = SA / N;
        double lo2 = (SB - SA) / N;
        double cnt = SC / N;
        out[0] = (float)(lo1 * (1.0 - cnt) + lo2 * cnt);
    }
}

extern "C" void kernel_launch(void* const* d_in, const int* in_sizes, int n_in,
                              void* d_out, int out_size) {
    (void)in_sizes; (void)n_in; (void)out_size;
    const float*     logit  = (const float*)d_in[0];
    const long long* target = (const long long*)d_in[1];
    const float*     image  = (const float*)d_in[2];
    const float*     depth  = (const float*)d_in[3];
    const float*     dstm   = (const float*)d_in[4];
    float* out = (float*)d_out;

    k_zero<<<1, 256>>>();
    k_prep<<<NPIX / 256, 256>>>(logit, target, image, depth, dstm);
    k_rows<<<Hh, 128>>>(dstm);
    dim3 blk(32, 4);
    dim3 grd(Ww / TBX, Hh / TBY, Bn);
    k_crf<<<grd, blk>>>();
    k_final<<<1, 256>>>(out);
}

// round 14
// speedup vs baseline: 1.6555x; 1.6555x over previous
#include <cuda_runtime.h>
#include <cuda_fp16.h>

#define Hh 256
#define Ww 512
#define Bn 4
#define SPANK 11
#define NOFF 242
#define NPIX (Bn*Hh*Ww)

#define RGB_S 8.493218083f
#define DEP_S 4.2466090415f

#define TBX 32
#define TBY 16
#define HYr 27
#define NHX 57
#define ROWB0 448            // 28 words * 16B (fp16 rgbz, 2 px/word)
#define PLANE0 12096
#define BASE1 24192          // after 2 plane-0 copies
#define ROWB1 224            // 28 words * 8B (fp8 y0,y1,d, 2 px/word)
#define PLANE1 6048
#define SMEMB 36288

__device__ uint4  g_PK[NPIX];   // {r,g | b,z | fp8 y0|y1|d | unused}
__device__ float  g_aF[256], g_aB[256];
__device__ double g_ce[3];
__device__ float  g_rowFull[Hh];
__device__ float  g_rowHead[Hh][12];
__device__ float  g_rowTail[Hh][12];

__device__ __forceinline__ __half2 h2ex2(__half2 x) {
    unsigned r;
    asm("ex2.approx.f16x2 %0, %1;" : "=r"(r) : "r"(*(unsigned*)&x));
    return *(__half2*)&r;
}
__device__ __forceinline__ __half2 e2h(unsigned s) {
    unsigned r;
    asm("cvt.rn.f16x2.e4m3x2 %0, %1;" : "=r"(r) : "h"((unsigned short)s));
    return *(__half2*)&r;
}
__device__ __forceinline__ unsigned short h2e(float lo, float hi) {
    unsigned short r;
    asm("cvt.rn.satfinite.e4m3x2.f32 %0, %1, %2;" : "=h"(r) : "f"(hi), "f"(lo));
    return r;
}

__global__ void k_zero() {
    int t = threadIdx.x;
    if (t < 256) { g_aF[t] = 0.f; g_aB[t] = 0.f; }
    if (t < 3) g_ce[t] = 0.0;
}

__global__ void k_prep(const float* __restrict__ logit,
                       const long long* __restrict__ target,
                       const float* __restrict__ image,
                       const float* __restrict__ depth,
                       const float* __restrict__ dstm) {
    int idx = blockIdx.x * blockDim.x + threadIdx.x;
    float ce_d = 0.f, ce_a = 0.f, d_s = 0.f;
    if (idx < NPIX) {
        int b = idx / (Hh * Ww);
        int p = idx - b * (Hh * Ww);
        const float* lg = logit + (size_t)b * 3 * Hh * Ww + p;
        float l0 = lg[0], l1 = lg[Hh * Ww], l2 = lg[2 * Hh * Ww];
        float m = fmaxf(l0, fmaxf(l1, l2));
        float e0 = __expf(l0 - m), e1 = __expf(l1 - m), e2 = __expf(l2 - m);
        float s = e0 + e1 + e2;
        float inv = 1.f / s;
        const float* im = image + (size_t)b * 3 * Hh * Ww + p;
        float dv = dstm[idx];
        __half2 h0 = __floats2half2_rn(im[0] * RGB_S, im[Hh * Ww] * RGB_S);
        __half2 h1 = __floats2half2_rn(im[2 * Hh * Ww] * RGB_S, depth[idx] * DEP_S);
        unsigned short yy = h2e(e0 * inv, e1 * inv);   // bytes: y0 | y1<<8
        unsigned short dd = h2e(dv, 0.f);              // byte:  d
        uint4 pk;
        pk.x = *(unsigned*)&h0; pk.y = *(unsigned*)&h1;
        pk.z = (unsigned)yy | ((unsigned)dd << 16);
        pk.w = 0u;
        g_PK[idx] = pk;
        long long t = target[idx];
        float lt = (t == 0) ? l0 : ((t == 1) ? l1 : l2);
        float lce = m + __logf(s) - lt;
        ce_d = lce * dv; ce_a = lce; d_s = dv;
    }
    #pragma unroll
    for (int s = 16; s; s >>= 1) {
        ce_d += __shfl_xor_sync(0xffffffffu, ce_d, s);
        ce_a += __shfl_xor_sync(0xffffffffu, ce_a, s);
        d_s  += __shfl_xor_sync(0xffffffffu, d_s,  s);
    }
    __shared__ float r0[8], r1[8], r2[8];
    int lane = threadIdx.x & 31, w = threadIdx.x >> 5;
    if (lane == 0) { r0[w] = ce_d; r1[w] = ce_a; r2[w] = d_s; }
    __syncthreads();
    if (threadIdx.x == 0) {
        float a = 0.f, bb = 0.f, c = 0.f;
        #pragma unroll
        for (int i = 0; i < 8; i++) { a += r0[i]; bb += r1[i]; c += r2[i]; }
        atomicAdd(&g_ce[0], (double)a);
        atomicAdd(&g_ce[1], (double)bb);
        atomicAdd(&g_ce[2], (double)c);
    }
}

__global__ void k_rows(const float* __restrict__ dstm) {
    int x = blockIdx.x;
    int tid = threadIdx.x;
    int lane = tid & 31, w = tid >> 5;
    float psum = 0.f;
    for (int b = 0; b < Bn; b++) {
        const float* row = dstm + ((size_t)b * Hh + x) * Ww;
        for (int y = tid; y < Ww; y += 128) psum += row[y];
    }
    #pragma unroll
    for (int s = 16; s; s >>= 1) psum += __shfl_xor_sync(0xffffffffu, psum, s);
    __shared__ float wsum[4];
    if (lane == 0) wsum[w] = psum;
    __syncthreads();
    if (tid == 0)
        g_rowFull[x] = wsum[0] + wsum[1] + wsum[2] + wsum[3];
    if (tid < 32 && lane <= SPANK) {
        float h = 0.f;
        for (int y = 0; y < lane; y++)
            for (int b = 0; b < Bn; b++)
                h += dstm[((size_t)b * Hh + x) * Ww + y];
        g_rowHead[x][lane] = h;
        float t = 0.f;
        for (int e = 1; e <= lane; e++)
            for (int b = 0; b < Bn; b++)
                t += dstm[((size_t)b * Hh + x) * Ww + (Ww - e)];
        g_rowTail[x][lane] = t;
    }
}

// ---- CRF: lanes=offsets, half2 pixel pairs; plane1 in fp8 (8B/word) ----
__global__ __launch_bounds__(128, 4) void k_crf() {
    __shared__ __align__(16) unsigned char buf[SMEMB];
    const int b  = blockIdx.z;
    const int r0 = blockIdx.y * TBY;
    const int c0 = blockIdx.x * TBX;
    const int lane = threadIdx.x;
    const int w = threadIdx.y;
    const int tid = w * 32 + lane;

    unsigned short* H = (unsigned short*)buf;
    for (int i = tid; i < HYr * NHX; i += 128) {
        int hy = i / NHX, hx = i - hy * NHX;
        int gy = r0 - SPANK + hy;
        int gx = c0 - 12 + hx;
        unsigned rg = 0x56405640u, bz = 0x56405640u, yd = 0u;   // sentinel 100.0
        if (gy >= 0 && gy < Hh && gx >= 0 && gx < Ww) {
            uint4 pk = g_PK[(b * Hh + gy) * Ww + gx];
            rg = pk.x; bz = pk.y; yd = pk.z;
        }
        unsigned char y0b = yd & 0xff, y1b = (yd >> 8) & 0xff, db = (yd >> 16) & 0xff;
        if (hx < 56) {
            int s = hx & 1;
            int be = (hy * 28 + (hx >> 1)) * 8 + s;
            H[be + 0] = (unsigned short)rg;  H[be + 2] = (unsigned short)(rg >> 16);
            H[be + 4] = (unsigned short)bz;  H[be + 6] = (unsigned short)(bz >> 16);
            int b1 = BASE1 + (hy * 28 + (hx >> 1)) * 8 + s;
            buf[b1 + 0] = y0b; buf[b1 + 2] = y1b; buf[b1 + 4] = db;
        }
        if (hx >= 1) {
            int ho = hx - 1;
            int s = ho & 1;
            int bo = (PLANE0 / 2) + (hy * 28 + (ho >> 1)) * 8 + s;
            H[bo + 0] = (unsigned short)rg;  H[bo + 2] = (unsigned short)(rg >> 16);
            H[bo + 4] = (unsigned short)bz;  H[bo + 6] = (unsigned short)(bz >> 16);
            int b1 = BASE1 + PLANE1 + (hy * 28 + (ho >> 1)) * 8 + s;
            buf[b1 + 0] = y0b; buf[b1 + 2] = y1b; buf[b1 + 4] = db;
        }
    }

    // per-lane offset tables (arithmetic, as in the 137us kernel)
    int vAdj0[8], vAdj1[8];
    __half2 cd2h[8];
    #pragma unroll
    for (int g = 0; g < 8; g++) {
        int id = g * 32 + lane;
        if (id >= NOFF) id = 12;             // dummy; results land in slots>=242, unread
        int dx = id / 22 + 1;
        int r  = id - (dx - 1) * 22;
        int dy = r - SPANK; dy += (dy >= 0);
        cd2h[g] = __float2half2_rn(-0.7213475204444817f * (float)(dx*dx + dy*dy) * (1.f/36.f));
        if (dy & 1) {
            vAdj0[g] = PLANE0 - dx * ROWB0 - 8 * (dy + 1);
            vAdj1[g] = PLANE1 - dx * ROWB1 - 4 * (dy + 1);
        } else {
            vAdj0[g] = -dx * ROWB0 - 8 * dy;
            vAdj1[g] = -dx * ROWB1 - 4 * dy;
        }
    }

    __half2 aF2[8], aB2[8];
    float accF[8], accB[8];
    const __half2 zero2 = __float2half2_rn(0.f);
    const __half2 one2  = __float2half2_rn(1.f);
    #pragma unroll
    for (int g = 0; g < 8; g++) { aF2[g] = zero2; aB2[g] = zero2; accF[g] = 0.f; accB[g] = 0.f; }

    __syncthreads();
    const unsigned char* base = buf;

    for (int rr = 0; rr < 4; rr++) {
        int hy = SPANK + 4 * w + rr;
        int oR0 = hy * ROWB0 + 6 * 16;
        int oR1 = BASE1 + hy * ROWB1 + 6 * 8;
        for (int t = 0; t < 16; t++) {
            int o0a = oR0 + t * 16;
            int o1a = oR1 + t * 8;
            uint4 o0 = *(const uint4*)(base + o0a);
            uint2 o1 = *(const uint2*)(base + o1a);
            __half2 Ro = *(__half2*)&o0.x, Go = *(__half2*)&o0.y;
            __half2 Bo = *(__half2*)&o0.z, Zo = *(__half2*)&o0.w;
            __half2 Y0o = e2h(o1.x & 0xffff);
            __half2 Y1o = e2h(o1.x >> 16);
            __half2 Do  = e2h(o1.y & 0xffff);
            __half2 A2 = __hadd2(Y0o, Y1o);          // = 1 - y2o
            __half2 y2o = __hsub2(one2, A2);
            __half2 B2 = __hsub2(y2o, Y0o);
            __half2 C2 = __hsub2(y2o, Y1o);
            #pragma unroll
            for (int g = 0; g < 8; g++) {
                uint4 v0 = *(const uint4*)(base + (o0a + vAdj0[g]));
                uint2 v1 = *(const uint2*)(base + (o1a + vAdj1[g]));
                __half2 dR = __hsub2(Ro, *(__half2*)&v0.x);
                __half2 dG = __hsub2(Go, *(__half2*)&v0.y);
                __half2 dB = __hsub2(Bo, *(__half2*)&v0.z);
                __half2 dZ = __hsub2(Zo, *(__half2*)&v0.w);
                __half2 a1 = __hfma2(dR, __hneg2(dR), cd2h[g]);
                a1 = __hfma2(dG, __hneg2(dG), a1);
                a1 = __hfma2(dB, __hneg2(dB), a1);
                __half2 az = __hmul2(dZ, __hneg2(dZ));
                __half2 k2 = __hadd2(h2ex2(a1), h2ex2(az));   // 0 when v is halo (sentinel)
                __half2 ct = __hfma2(B2, e2h(v1.x & 0xffff), A2);
                ct = __hfma2(C2, e2h(v1.x >> 16), ct);
                __half2 kc = __hmul2(k2, ct);
                aF2[g] = __hfma2(kc, e2h(v1.y & 0xffff), aF2[g]);
                aB2[g] = __hfma2(kc, Do, aB2[g]);
            }
            if ((t & 7) == 7) {
                #pragma unroll
                for (int g = 0; g < 8; g++) {
                    float2 f = __half22float2(aF2[g]);
                    float2 bb = __half22float2(aB2[g]);
                    accF[g] += f.x + f.y;
                    accB[g] += bb.x + bb.y;
                    aF2[g] = zero2; aB2[g] = zero2;
                }
            }
        }
    }

    __syncthreads();
    float* red = (float*)buf;                  // [256][4 warps][2]
    #pragma unroll
    for (int g = 0; g < 8; g++) {
        int id = g * 32 + lane;                // unclamped: dummies land in 242..255
        red[(id * 4 + w) * 2 + 0] = accF[g];
        red[(id * 4 + w) * 2 + 1] = accB[g];
    }
    __syncthreads();
    for (int o = tid; o < NOFF; o += 128) {
        float f  = red[o * 8 + 0] + red[o * 8 + 2] + red[o * 8 + 4] + red[o * 8 + 6];
        float bb = red[o * 8 + 1] + red[o * 8 + 3] + red[o * 8 + 5] + red[o * 8 + 7];
        atomicAdd(&g_aF[o], f);
        atomicAdd(&g_aB[o], bb);
    }
}

__global__ void k_final(float* __restrict__ out) {
    __shared__ float  sR[23][Hh];
    __shared__ double sFull[23], sHead[23][12], sTail[23][12];
    __shared__ double rect[23 * 23];
    __shared__ double red[256];
    int tid = threadIdx.x;
    int lane = tid & 31, w8 = tid >> 5;
    {
        int x = tid;
        float full = g_rowFull[x];
        float head[12], tail[12];
        #pragma unroll
        for (int i = 0; i < 12; i++) { head[i] = g_rowHead[x][i]; tail[i] = g_rowTail[x][i]; }
        #pragma unroll
        for (int yi = 0; yi < 23; yi++) {
            int dy = yi - SPANK;
            int c = dy < 0 ? -dy : 0;
            int e = dy > 0 ? dy : 0;
            sR[yi][x] = full - head[c] - tail[e];
        }
    }
    __syncthreads();
    for (int yi = w8; yi < 23; yi += 8) {
        float p = 0.f;
        for (int x = lane; x < Hh; x += 32) p += sR[yi][x];
        #pragma unroll
        for (int s = 16; s; s >>= 1) p += __shfl_xor_sync(0xffffffffu, p, s);
        if (lane == 0) sFull[yi] = (double)p;
        if (lane <= SPANK) {
            float h = 0.f;
            for (int x = 0; x < lane; x++) h += sR[yi][x];
            sHead[yi][lane] = (double)h;
            float t = 0.f;
            for (int e = 1; e <= lane; e++) t += sR[yi][Hh - e];
            sTail[yi][lane] = (double)t;
        }
    }
    __syncthreads();
    for (int t = tid; t < 23 * 23; t += 256) {
        int xi = t / 23, yi = t - xi * 23;
        int dx = xi - SPANK;
        int a = dx < 0 ? -dx : 0;
        int bb = dx > 0 ? dx : 0;
        rect[t] = sFull[yi] - sHead[yi][a] - sTail[yi][bb];
    }
    __syncthreads();
    double e = 0.0;
    if (tid < NOFF) {
        int dx = tid / 22 + 1;
        int r = tid - (dx - 1) * 22;
        int dy = r - SPANK;
        dy += (dy >= 0);
        double denF = rect[(SPANK - dx) * 23 + (SPANK - dy)];
        double denB = rect[(SPANK + dx) * 23 + (SPANK + dy)];
        e = (double)g_aF[tid] / denF + (double)g_aB[tid] / denB;
    }
    red[tid] = e;
    __syncthreads();
    for (int s = 128; s; s >>= 1) {
        if (tid < s) red[tid] += red[tid + s];
        __syncthreads();
    }
    if (tid == 0) {
        out[1] = (float)(red[0] / 529.0);
        double N = (double)NPIX;
        double SA = g_ce[0], SB = g_ce[1], SC = g_ce[2];
        double lo1 = SA / N;
        double lo2 = (SB - SA) / N;
        double cnt = SC / N;
        out[0] = (float)(lo1 * (1.0 - cnt) + lo2 * cnt);
    }
}

extern "C" void kernel_launch(void* const* d_in, const int* in_sizes, int n_in,
                              void* d_out, int out_size) {
    (void)in_sizes; (void)n_in; (void)out_size;
    const float*     logit  = (const float*)d_in[0];
    const long long* target = (const long long*)d_in[1];
    const float*     image  = (const float*)d_in[2];
    const float*     depth  = (const float*)d_in[3];
    const float*     dstm   = (const float*)d_in[4];
    float* out = (float*)d_out;

    k_zero<<<1, 256>>>();
    k_prep<<<NPIX / 256, 256>>>(logit, target, image, depth, dstm);
    k_rows<<<Hh, 128>>>(dstm);
    dim3 blk(32, 4);
    dim3 grd(Ww / TBX, Hh / TBY, Bn);
    k_crf<<<grd, blk>>>();
    k_final<<<1, 256>>>(out);
}

// round 15
// speedup vs baseline: 1.6849x; 1.0178x over previous
#include <cuda_runtime.h>
#include <cuda_fp16.h>

#define Hh 256
#define Ww 512
#define Bn 4
#define SPANK 11
#define NOFF 242
#define NPIX (Bn*Hh*Ww)

#define RGB_S 8.493218083f
#define DEP_S 4.2466090415f

#define TBX 32
#define TBY 16
#define HYr 27
#define NHX 57
#define ROWB0 448            // 28 words * 16B (fp16 rgbz, 2 px/word)
#define PLANE0 12096
#define BASE1 24192          // after 2 plane-0 copies
#define ROWB1 224            // 28 words * 8B (fp8 y0,y1,d, 2 px/word)
#define PLANE1 6048
#define SMEMB 36288

__device__ uint4  g_PK[NPIX];   // {r,g | b,z | fp8 y0|y1|d | unused}
__device__ float  g_aF[256], g_aB[256];
__device__ double g_ce[3];
__device__ float  g_rowFull[Hh];
__device__ float  g_rowHead[Hh][12];
__device__ float  g_rowTail[Hh][12];

__device__ __forceinline__ __half2 h2ex2(__half2 x) {
    unsigned r;
    asm("ex2.approx.f16x2 %0, %1;" : "=r"(r) : "r"(*(unsigned*)&x));
    return *(__half2*)&r;
}
__device__ __forceinline__ __half2 e2h(unsigned s) {
    unsigned r;
    asm("cvt.rn.f16x2.e4m3x2 %0, %1;" : "=r"(r) : "h"((unsigned short)s));
    return *(__half2*)&r;
}
__device__ __forceinline__ unsigned short h2e(float lo, float hi) {
    unsigned short r;
    asm("cvt.rn.satfinite.e4m3x2.f32 %0, %1, %2;" : "=h"(r) : "f"(hi), "f"(lo));
    return r;
}

__global__ void k_zero() {
    int t = threadIdx.x;
    if (t < 256) { g_aF[t] = 0.f; g_aB[t] = 0.f; }
    if (t < 3) g_ce[t] = 0.0;
}

__global__ void k_prep(const float* __restrict__ logit,
                       const long long* __restrict__ target,
                       const float* __restrict__ image,
                       const float* __restrict__ depth,
                       const float* __restrict__ dstm) {
    int idx = blockIdx.x * blockDim.x + threadIdx.x;
    float ce_d = 0.f, ce_a = 0.f, d_s = 0.f;
    if (idx < NPIX) {
        int b = idx / (Hh * Ww);
        int p = idx - b * (Hh * Ww);
        const float* lg = logit + (size_t)b * 3 * Hh * Ww + p;
        float l0 = lg[0], l1 = lg[Hh * Ww], l2 = lg[2 * Hh * Ww];
        float m = fmaxf(l0, fmaxf(l1, l2));
        float e0 = __expf(l0 - m), e1 = __expf(l1 - m), e2 = __expf(l2 - m);
        float s = e0 + e1 + e2;
        float inv = 1.f / s;
        const float* im = image + (size_t)b * 3 * Hh * Ww + p;
        float dv = dstm[idx];
        __half2 h0 = __floats2half2_rn(im[0] * RGB_S, im[Hh * Ww] * RGB_S);
        __half2 h1 = __floats2half2_rn(im[2 * Hh * Ww] * RGB_S, depth[idx] * DEP_S);
        unsigned short yy = h2e(e0 * inv, e1 * inv);   // bytes: y0 | y1<<8
        unsigned short dd = h2e(dv, 0.f);              // byte:  d
        uint4 pk;
        pk.x = *(unsigned*)&h0; pk.y = *(unsigned*)&h1;
        pk.z = (unsigned)yy | ((unsigned)dd << 16);
        pk.w = 0u;
        g_PK[idx] = pk;
        long long t = target[idx];
        float lt = (t == 0) ? l0 : ((t == 1) ? l1 : l2);
        float lce = m + __logf(s) - lt;
        ce_d = lce * dv; ce_a = lce; d_s = dv;
    }
    #pragma unroll
    for (int s = 16; s; s >>= 1) {
        ce_d += __shfl_xor_sync(0xffffffffu, ce_d, s);
        ce_a += __shfl_xor_sync(0xffffffffu, ce_a, s);
        d_s  += __shfl_xor_sync(0xffffffffu, d_s,  s);
    }
    __shared__ float r0[8], r1[8], r2[8];
    int lane = threadIdx.x & 31, w = threadIdx.x >> 5;
    if (lane == 0) { r0[w] = ce_d; r1[w] = ce_a; r2[w] = d_s; }
    __syncthreads();
    if (threadIdx.x == 0) {
        float a = 0.f, bb = 0.f, c = 0.f;
        #pragma unroll
        for (int i = 0; i < 8; i++) { a += r0[i]; bb += r1[i]; c += r2[i]; }
        atomicAdd(&g_ce[0], (double)a);
        atomicAdd(&g_ce[1], (double)bb);
        atomicAdd(&g_ce[2], (double)c);
    }
}

__global__ void k_rows(const float* __restrict__ dstm) {
    int x = blockIdx.x;
    int tid = threadIdx.x;
    int lane = tid & 31, w = tid >> 5;
    float psum = 0.f;
    for (int b = 0; b < Bn; b++) {
        const float* row = dstm + ((size_t)b * Hh + x) * Ww;
        for (int y = tid; y < Ww; y += 128) psum += row[y];
    }
    #pragma unroll
    for (int s = 16; s; s >>= 1) psum += __shfl_xor_sync(0xffffffffu, psum, s);
    __shared__ float wsum[4];
    if (lane == 0) wsum[w] = psum;
    __syncthreads();
    if (tid == 0)
        g_rowFull[x] = wsum[0] + wsum[1] + wsum[2] + wsum[3];
    if (tid < 32 && lane <= SPANK) {
        float h = 0.f;
        for (int y = 0; y < lane; y++)
            for (int b = 0; b < Bn; b++)
                h += dstm[((size_t)b * Hh + x) * Ww + y];
        g_rowHead[x][lane] = h;
        float t = 0.f;
        for (int e = 1; e <= lane; e++)
            for (int b = 0; b < Bn; b++)
                t += dstm[((size_t)b * Hh + x) * Ww + (Ww - e)];
        g_rowTail[x][lane] = t;
    }
}

// ---- CRF: lanes=offsets, half2 pixel pairs; plane1 fp8; 5 CTAs/SM ----
__global__ __launch_bounds__(128, 5) void k_crf() {
    __shared__ __align__(16) unsigned char buf[SMEMB];
    const int b  = blockIdx.z;
    const int r0 = blockIdx.y * TBY;
    const int c0 = blockIdx.x * TBX;
    const int lane = threadIdx.x;
    const int w = threadIdx.y;
    const int tid = w * 32 + lane;

    unsigned short* H = (unsigned short*)buf;
    for (int i = tid; i < HYr * NHX; i += 128) {
        int hy = i / NHX, hx = i - hy * NHX;
        int gy = r0 - SPANK + hy;
        int gx = c0 - 12 + hx;
        unsigned rg = 0x56405640u, bz = 0x56405640u, yd = 0u;   // sentinel 100.0
        if (gy >= 0 && gy < Hh && gx >= 0 && gx < Ww) {
            uint4 pk = g_PK[(b * Hh + gy) * Ww + gx];
            rg = pk.x; bz = pk.y; yd = pk.z;
        }
        unsigned char y0b = yd & 0xff, y1b = (yd >> 8) & 0xff, db = (yd >> 16) & 0xff;
        if (hx < 56) {
            int s = hx & 1;
            int be = (hy * 28 + (hx >> 1)) * 8 + s;
            H[be + 0] = (unsigned short)rg;  H[be + 2] = (unsigned short)(rg >> 16);
            H[be + 4] = (unsigned short)bz;  H[be + 6] = (unsigned short)(bz >> 16);
            int b1 = BASE1 + (hy * 28 + (hx >> 1)) * 8 + s;
            buf[b1 + 0] = y0b; buf[b1 + 2] = y1b; buf[b1 + 4] = db;
        }
        if (hx >= 1) {
            int ho = hx - 1;
            int s = ho & 1;
            int bo = (PLANE0 / 2) + (hy * 28 + (ho >> 1)) * 8 + s;
            H[bo + 0] = (unsigned short)rg;  H[bo + 2] = (unsigned short)(rg >> 16);
            H[bo + 4] = (unsigned short)bz;  H[bo + 6] = (unsigned short)(bz >> 16);
            int b1 = BASE1 + PLANE1 + (hy * 28 + (ho >> 1)) * 8 + s;
            buf[b1 + 0] = y0b; buf[b1 + 2] = y1b; buf[b1 + 4] = db;
        }
    }

    // per-lane offset tables (vAdj1 derived as vAdj0/2 in the loop: exact, saves 8 regs)
    int vAdj0[8];
    __half2 cd2h[8];
    #pragma unroll
    for (int g = 0; g < 8; g++) {
        int id = g * 32 + lane;
        if (id >= NOFF) id = 12;             // dummy; results land in slots>=242, unread
        int dx = id / 22 + 1;
        int r  = id - (dx - 1) * 22;
        int dy = r - SPANK; dy += (dy >= 0);
        cd2h[g] = __float2half2_rn(-0.7213475204444817f * (float)(dx*dx + dy*dy) * (1.f/36.f));
        vAdj0[g] = (dy & 1) ? (PLANE0 - dx * ROWB0 - 8 * (dy + 1))
                            : (-dx * ROWB0 - 8 * dy);
    }

    __half2 aF2[8], aB2[8];
    float accF[8], accB[8];
    const __half2 zero2 = __float2half2_rn(0.f);
    const __half2 one2  = __float2half2_rn(1.f);
    #pragma unroll
    for (int g = 0; g < 8; g++) { aF2[g] = zero2; aB2[g] = zero2; accF[g] = 0.f; accB[g] = 0.f; }

    __syncthreads();
    const unsigned char* base = buf;

    for (int rr = 0; rr < 4; rr++) {
        int hy = SPANK + 4 * w + rr;
        int oR0 = hy * ROWB0 + 6 * 16;
        int oR1 = BASE1 + hy * ROWB1 + 6 * 8;
        for (int t = 0; t < 16; t++) {
            int o0a = oR0 + t * 16;
            int o1a = oR1 + t * 8;
            uint4 o0 = *(const uint4*)(base + o0a);
            uint2 o1 = *(const uint2*)(base + o1a);
            __half2 Ro = *(__half2*)&o0.x, Go = *(__half2*)&o0.y;
            __half2 Bo = *(__half2*)&o0.z, Zo = *(__half2*)&o0.w;
            __half2 Y0o = e2h(o1.x & 0xffff);
            __half2 Y1o = e2h(o1.x >> 16);
            __half2 Do  = e2h(o1.y & 0xffff);
            __half2 A2 = __hadd2(Y0o, Y1o);          // = 1 - y2o
            __half2 y2o = __hsub2(one2, A2);
            __half2 B2 = __hsub2(y2o, Y0o);
            __half2 C2 = __hsub2(y2o, Y1o);
            #pragma unroll
            for (int g = 0; g < 8; g++) {
                uint4 v0 = *(const uint4*)(base + (o0a + vAdj0[g]));
                uint2 v1 = *(const uint2*)(base + (o1a + (vAdj0[g] / 2)));
                __half2 dR = __hsub2(Ro, *(__half2*)&v0.x);
                __half2 dG = __hsub2(Go, *(__half2*)&v0.y);
                __half2 dB = __hsub2(Bo, *(__half2*)&v0.z);
                __half2 dZ = __hsub2(Zo, *(__half2*)&v0.w);
                __half2 a1 = __hfma2(dR, __hneg2(dR), cd2h[g]);
                a1 = __hfma2(dG, __hneg2(dG), a1);
                a1 = __hfma2(dB, __hneg2(dB), a1);
                __half2 az = __hmul2(dZ, __hneg2(dZ));
                __half2 k2 = __hadd2(h2ex2(a1), h2ex2(az));   // 0 when v is halo (sentinel)
                __half2 ct = __hfma2(B2, e2h(v1.x & 0xffff), A2);
                ct = __hfma2(C2, e2h(v1.x >> 16), ct);
                __half2 kc = __hmul2(k2, ct);
                aF2[g] = __hfma2(kc, e2h(v1.y & 0xffff), aF2[g]);
                aB2[g] = __hfma2(kc, Do, aB2[g]);
            }
            if (t == 15) {                            // dump once per rr
                #pragma unroll
                for (int g = 0; g < 8; g++) {
                    float2 f = __half22float2(aF2[g]);
                    float2 bb = __half22float2(aB2[g]);
                    accF[g] += f.x + f.y;
                    accB[g] += bb.x + bb.y;
                    aF2[g] = zero2; aB2[g] = zero2;
                }
            }
        }
    }

    __syncthreads();
    float* red = (float*)buf;                  // [256][4 warps][2]
    #pragma unroll
    for (int g = 0; g < 8; g++) {
        int id = g * 32 + lane;                // dummies land in 242..255, unread
        red[(id * 4 + w) * 2 + 0] = accF[g];
        red[(id * 4 + w) * 2 + 1] = accB[g];
    }
    __syncthreads();
    for (int o = tid; o < NOFF; o += 128) {
        float f  = red[o * 8 + 0] + red[o * 8 + 2] + red[o * 8 + 4] + red[o * 8 + 6];
        float bb = red[o * 8 + 1] + red[o * 8 + 3] + red[o * 8 + 5] + red[o * 8 + 7];
        atomicAdd(&g_aF[o], f);
        atomicAdd(&g_aB[o], bb);
    }
}

__global__ void k_final(float* __restrict__ out) {
    __shared__ float  sR[23][Hh];
    __shared__ double sFull[23], sHead[23][12], sTail[23][12];
    __shared__ double rect[23 * 23];
    __shared__ double red[256];
    int tid = threadIdx.x;
    int lane = tid & 31, w8 = tid >> 5;
    {
        int x = tid;
        float full = g_rowFull[x];
        float head[12], tail[12];
        #pragma unroll
        for (int i = 0; i < 12; i++) { head[i] = g_rowHead[x][i]; tail[i] = g_rowTail[x][i]; }
        #pragma unroll
        for (int yi = 0; yi < 23; yi++) {
            int dy = yi - SPANK;
            int c = dy < 0 ? -dy : 0;
            int e = dy > 0 ? dy : 0;
            sR[yi][x] = full - head[c] - tail[e];
        }
    }
    __syncthreads();
    for (int yi = w8; yi < 23; yi += 8) {
        float p = 0.f;
        for (int x = lane; x < Hh; x += 32) p += sR[yi][x];
        #pragma unroll
        for (int s = 16; s; s >>= 1) p += __shfl_xor_sync(0xffffffffu, p, s);
        if (lane == 0) sFull[yi] = (double)p;
        if (lane <= SPANK) {
            float h = 0.f;
            for (int x = 0; x < lane; x++) h += sR[yi][x];
            sHead[yi][lane] = (double)h;
            float t = 0.f;
            for (int e = 1; e <= lane; e++) t += sR[yi][Hh - e];
            sTail[yi][lane] = (double)t;
        }
    }
    __syncthreads();
    for (int t = tid; t < 23 * 23; t += 256) {
        int xi = t / 23, yi = t - xi * 23;
        int dx = xi - SPANK;
        int a = dx < 0 ? -dx : 0;
        int bb = dx > 0 ? dx : 0;
        rect[t] = sFull[yi] - sHead[yi][a] - sTail[yi][bb];
    }
    __syncthreads();
    double e = 0.0;
    if (tid < NOFF) {
        int dx = tid / 22 + 1;
        int r = tid - (dx - 1) * 22;
        int dy = r - SPANK;
        dy += (dy >= 0);
        double denF = rect[(SPANK - dx) * 23 + (SPANK - dy)];
        double denB = rect[(SPANK + dx) * 23 + (SPANK + dy)];
        e = (double)g_aF[tid] / denF + (double)g_aB[tid] / denB;
    }
    red[tid] = e;
    __syncthreads();
    for (int s = 128; s; s >>= 1) {
        if (tid < s) red[tid] += red[tid + s];
        __syncthreads();
    }
    if (tid == 0) {
        out[1] = (float)(red[0] / 529.0);
        double N = (double)NPIX;
        double SA = g_ce[0], SB = g_ce[1], SC = g_ce[2];
        double lo1 = SA / N;
        double lo2 = (SB - SA) / N;
        double cnt = SC / N;
        out[0] = (float)(lo1 * (1.0 - cnt) + lo2 * cnt);
    }
}

extern "C" void kernel_launch(void* const* d_in, const int* in_sizes, int n_in,
                              void* d_out, int out_size) {
    (void)in_sizes; (void)n_in; (void)out_size;
    const float*     logit  = (const float*)d_in[0];
    const long long* target = (const long long*)d_in[1];
    const float*     image  = (const float*)d_in[2];
    const float*     depth  = (const float*)d_in[3];
    const float*     dstm   = (const float*)d_in[4];
    float* out = (float*)d_out;

    k_zero<<<1, 256>>>();
    k_prep<<<NPIX / 256, 256>>>(logit, target, image, depth, dstm);
    k_rows<<<Hh, 128>>>(dstm);
    dim3 blk(32, 4);
    dim3 grd(Ww / TBX, Hh / TBY, Bn);
    k_crf<<<grd, blk>>>();
    k_final<<<1, 256>>>(out);
}